// round 1
// baseline (speedup 1.0000x reference)
#include <cuda_runtime.h>
#include <math_constants.h>

// Problem constants
#define BB   4
#define SS   2048
#define DD   1024
#define HH   16
#define DK   64
#define DOUT 1024

// Scratch (static device globals: allocation-free rule)
__device__ float g_Q[(size_t)BB * HH * SS * DK];     // [B,H,S,DK] 32MB
__device__ float g_K[(size_t)BB * HH * SS * DK];
__device__ float g_V[(size_t)BB * HH * SS * DK];
__device__ float g_cat[(size_t)BB * SS * HH * DK];   // [B,S,H*DK] 32MB

// ---------------------------------------------------------------------------
// Kernel 1: QKV projections.  For each (proj, b, h):
//   out[b,h,:,:] = x[b] (2048x1024) @ W[h] (1024x64) + bias[h]
// Tiling: BM=128, BN=64(full DK), BK=16, 256 threads, 8x4 micro-tile.
// ---------------------------------------------------------------------------
__global__ __launch_bounds__(256) void qkv_kernel(
    const float* __restrict__ x,
    const float* __restrict__ Wq, const float* __restrict__ bq,
    const float* __restrict__ Wk, const float* __restrict__ bk,
    const float* __restrict__ Wv, const float* __restrict__ bv)
{
    const int proj = blockIdx.z;          // 0=Q 1=K 2=V
    const int bh   = blockIdx.y;          // b*16+h
    const int b    = bh >> 4;
    const int h    = bh & 15;
    const int m0   = blockIdx.x * 128;

    const float* W;
    const float* bias;
    float* out;
    if (proj == 0)      { W = Wq; bias = bq; out = g_Q; }
    else if (proj == 1) { W = Wk; bias = bk; out = g_K; }
    else                { W = Wv; bias = bv; out = g_V; }
    W    += (size_t)h * DD * DK;
    bias += h * DK;
    out  += ((size_t)bh * SS + m0) * DK;
    const float* A = x + (size_t)b * SS * DD + (size_t)m0 * DD;

    __shared__ float As[16][128];   // [k][m]  (transposed)
    __shared__ float Ws[16][64];    // [k][n]

    const int tid = threadIdx.x;
    const int ty  = tid >> 4;       // 0..15 -> rows ty*8..+7
    const int tx  = tid & 15;       // 0..15 -> cols tx*4..+3

    float acc[8][4];
    #pragma unroll
    for (int i = 0; i < 8; i++)
        #pragma unroll
        for (int j = 0; j < 4; j++) acc[i][j] = 0.f;

    for (int k0 = 0; k0 < DD; k0 += 16) {
        // A tile: 128 rows x 16 cols = 512 float4, 2 per thread (store transposed)
        #pragma unroll
        for (int u = 0; u < 2; u++) {
            int idx = tid + u * 256;
            int row = idx >> 2;
            int c4  = idx & 3;
            float4 v = *(const float4*)(A + (size_t)row * DD + k0 + c4 * 4);
            As[c4 * 4 + 0][row] = v.x;
            As[c4 * 4 + 1][row] = v.y;
            As[c4 * 4 + 2][row] = v.z;
            As[c4 * 4 + 3][row] = v.w;
        }
        // W tile: 16 rows x 64 cols = 256 float4, 1 per thread
        {
            int r  = tid >> 4;
            int c4 = tid & 15;
            float4 v = *(const float4*)(W + (size_t)(k0 + r) * DK + c4 * 4);
            *(float4*)&Ws[r][c4 * 4] = v;
        }
        __syncthreads();
        #pragma unroll
        for (int k = 0; k < 16; k++) {
            float4 a0 = *(const float4*)&As[k][ty * 8];
            float4 a1 = *(const float4*)&As[k][ty * 8 + 4];
            float4 b0 = *(const float4*)&Ws[k][tx * 4];
            float ra[8] = {a0.x, a0.y, a0.z, a0.w, a1.x, a1.y, a1.z, a1.w};
            float rb[4] = {b0.x, b0.y, b0.z, b0.w};
            #pragma unroll
            for (int i = 0; i < 8; i++)
                #pragma unroll
                for (int j = 0; j < 4; j++)
                    acc[i][j] += ra[i] * rb[j];
        }
        __syncthreads();
    }

    float4 bv4 = *(const float4*)(bias + tx * 4);
    #pragma unroll
    for (int i = 0; i < 8; i++) {
        int m = ty * 8 + i;
        float4 o;
        o.x = acc[i][0] + bv4.x;
        o.y = acc[i][1] + bv4.y;
        o.z = acc[i][2] + bv4.z;
        o.w = acc[i][3] + bv4.w;
        *(float4*)(out + (size_t)m * DK + tx * 4) = o;
    }
}

// ---------------------------------------------------------------------------
// Kernel 2: flash attention per (b,h), 128-query tiles, 64-key tiles.
// Online softmax; per-row m/l replicated in registers across the 16 lanes
// owning each row (row spread over tx); shfl-xor reductions over 16-lane group.
// ---------------------------------------------------------------------------
__global__ __launch_bounds__(256) void attn_kernel()
{
    extern __shared__ float sm[];
    float* Qst = sm;                    // [64][128]  Q transposed [k][m]
    float* Kst = Qst + 64 * 128;        // [64][64]   K transposed [k][n]
    float* Vs  = Kst + 64 * 64;         // [64][64]   V [n][d]
    float* Pst = Vs  + 64 * 64;         // [64][128]  P transposed [n][m]

    const int bh = blockIdx.y;
    const int b  = bh >> 4;
    const int h  = bh & 15;
    const int q0 = blockIdx.x * 128;

    const float* Qp = g_Q + ((size_t)bh * SS + q0) * DK;
    const float* Kp = g_K + (size_t)bh * SS * DK;
    const float* Vp = g_V + (size_t)bh * SS * DK;

    const int tid = threadIdx.x;
    const int ty  = tid >> 4;   // rows ty*8..+7
    const int tx  = tid & 15;   // cols tx*4..+3

    // Load Q tile transposed: 128 rows x 64 = 2048 float4, 8 per thread
    #pragma unroll
    for (int u = 0; u < 8; u++) {
        int idx = tid + u * 256;
        int m   = idx >> 4;
        int k4  = idx & 15;
        float4 v = *(const float4*)(Qp + (size_t)m * DK + k4 * 4);
        Qst[(k4 * 4 + 0) * 128 + m] = v.x;
        Qst[(k4 * 4 + 1) * 128 + m] = v.y;
        Qst[(k4 * 4 + 2) * 128 + m] = v.z;
        Qst[(k4 * 4 + 3) * 128 + m] = v.w;
    }

    float O[8][4];
    float rm[8], rl[8];
    #pragma unroll
    for (int i = 0; i < 8; i++) {
        rm[i] = -CUDART_INF_F;
        rl[i] = 0.f;
        #pragma unroll
        for (int j = 0; j < 4; j++) O[i][j] = 0.f;
    }

    const float scale = 0.125f;  // 1/sqrt(64)

    for (int t = 0; t < SS; t += 64) {
        __syncthreads();   // protect Kst/Vs/Pst from previous iteration readers
        // Load K (transposed) and V (direct): 64x64 each -> 4 float4/thread each
        #pragma unroll
        for (int u = 0; u < 4; u++) {
            int idx = tid + u * 256;
            int n   = idx >> 4;
            int k4  = idx & 15;
            float4 kv = *(const float4*)(Kp + (size_t)(t + n) * DK + k4 * 4);
            Kst[(k4 * 4 + 0) * 64 + n] = kv.x;
            Kst[(k4 * 4 + 1) * 64 + n] = kv.y;
            Kst[(k4 * 4 + 2) * 64 + n] = kv.z;
            Kst[(k4 * 4 + 3) * 64 + n] = kv.w;
            float4 vv = *(const float4*)(Vp + (size_t)(t + n) * DK + k4 * 4);
            *(float4*)&Vs[n * 64 + k4 * 4] = vv;
        }
        __syncthreads();

        // S = Q @ K^T  (128 x 64 over k=64)
        float s[8][4];
        #pragma unroll
        for (int i = 0; i < 8; i++)
            #pragma unroll
            for (int j = 0; j < 4; j++) s[i][j] = 0.f;

        #pragma unroll 8
        for (int k = 0; k < 64; k++) {
            float4 a0 = *(const float4*)&Qst[k * 128 + ty * 8];
            float4 a1 = *(const float4*)&Qst[k * 128 + ty * 8 + 4];
            float4 b0 = *(const float4*)&Kst[k * 64 + tx * 4];
            float ra[8] = {a0.x, a0.y, a0.z, a0.w, a1.x, a1.y, a1.z, a1.w};
            float rb[4] = {b0.x, b0.y, b0.z, b0.w};
            #pragma unroll
            for (int i = 0; i < 8; i++)
                #pragma unroll
                for (int j = 0; j < 4; j++)
                    s[i][j] += ra[i] * rb[j];
        }

        // Online softmax per row (rows owned by 16-lane groups with same ty)
        #pragma unroll
        for (int i = 0; i < 8; i++) {
            float s0 = s[i][0] * scale;
            float s1 = s[i][1] * scale;
            float s2 = s[i][2] * scale;
            float s3 = s[i][3] * scale;
            float tmax = fmaxf(fmaxf(s0, s1), fmaxf(s2, s3));
            #pragma unroll
            for (int off = 8; off; off >>= 1)
                tmax = fmaxf(tmax, __shfl_xor_sync(0xffffffffu, tmax, off));
            float nm    = fmaxf(rm[i], tmax);
            float alpha = __expf(rm[i] - nm);
            float p0 = __expf(s0 - nm);
            float p1 = __expf(s1 - nm);
            float p2 = __expf(s2 - nm);
            float p3 = __expf(s3 - nm);
            float ps = (p0 + p1) + (p2 + p3);
            #pragma unroll
            for (int off = 8; off; off >>= 1)
                ps += __shfl_xor_sync(0xffffffffu, ps, off);
            rl[i] = rl[i] * alpha + ps;
            rm[i] = nm;
            O[i][0] *= alpha; O[i][1] *= alpha; O[i][2] *= alpha; O[i][3] *= alpha;
            int m = ty * 8 + i;
            Pst[(tx * 4 + 0) * 128 + m] = p0;
            Pst[(tx * 4 + 1) * 128 + m] = p1;
            Pst[(tx * 4 + 2) * 128 + m] = p2;
            Pst[(tx * 4 + 3) * 128 + m] = p3;
        }
        __syncthreads();

        // O += P @ V  (128 x 64 over n=64)
        #pragma unroll 8
        for (int n = 0; n < 64; n++) {
            float4 a0 = *(const float4*)&Pst[n * 128 + ty * 8];
            float4 a1 = *(const float4*)&Pst[n * 128 + ty * 8 + 4];
            float4 vb = *(const float4*)&Vs[n * 64 + tx * 4];
            float pa[8] = {a0.x, a0.y, a0.z, a0.w, a1.x, a1.y, a1.z, a1.w};
            float rb[4] = {vb.x, vb.y, vb.z, vb.w};
            #pragma unroll
            for (int i = 0; i < 8; i++)
                #pragma unroll
                for (int j = 0; j < 4; j++)
                    O[i][j] += pa[i] * rb[j];
        }
    }

    // Epilogue: normalize and write to concatenated layout [B,S,H*DK]
    #pragma unroll
    for (int i = 0; i < 8; i++) {
        float inv = 1.0f / rl[i];
        int m = q0 + ty * 8 + i;
        float4 o;
        o.x = O[i][0] * inv;
        o.y = O[i][1] * inv;
        o.z = O[i][2] * inv;
        o.w = O[i][3] * inv;
        *(float4*)(g_cat + ((size_t)(b * SS + m)) * (HH * DK) + h * DK + tx * 4) = o;
    }
}

// ---------------------------------------------------------------------------
// Kernel 3: output projection  out = cat(8192x1024) @ Wo(1024x1024) + bo
// Same 128x64x16 tiling.
// ---------------------------------------------------------------------------
__global__ __launch_bounds__(256) void out_kernel(
    const float* __restrict__ Wo, const float* __restrict__ bo,
    float* __restrict__ out)
{
    const int m0 = blockIdx.x * 128;
    const int n0 = blockIdx.y * 64;
    const float* A = g_cat + (size_t)m0 * (HH * DK);

    __shared__ float As[16][128];
    __shared__ float Ws[16][64];

    const int tid = threadIdx.x;
    const int ty  = tid >> 4;
    const int tx  = tid & 15;

    float acc[8][4];
    #pragma unroll
    for (int i = 0; i < 8; i++)
        #pragma unroll
        for (int j = 0; j < 4; j++) acc[i][j] = 0.f;

    for (int k0 = 0; k0 < HH * DK; k0 += 16) {
        #pragma unroll
        for (int u = 0; u < 2; u++) {
            int idx = tid + u * 256;
            int row = idx >> 2;
            int c4  = idx & 3;
            float4 v = *(const float4*)(A + (size_t)row * (HH * DK) + k0 + c4 * 4);
            As[c4 * 4 + 0][row] = v.x;
            As[c4 * 4 + 1][row] = v.y;
            As[c4 * 4 + 2][row] = v.z;
            As[c4 * 4 + 3][row] = v.w;
        }
        {
            int r  = tid >> 4;
            int c4 = tid & 15;
            float4 v = *(const float4*)(Wo + (size_t)(k0 + r) * DOUT + n0 + c4 * 4);
            *(float4*)&Ws[r][c4 * 4] = v;
        }
        __syncthreads();
        #pragma unroll
        for (int k = 0; k < 16; k++) {
            float4 a0 = *(const float4*)&As[k][ty * 8];
            float4 a1 = *(const float4*)&As[k][ty * 8 + 4];
            float4 b0 = *(const float4*)&Ws[k][tx * 4];
            float ra[8] = {a0.x, a0.y, a0.z, a0.w, a1.x, a1.y, a1.z, a1.w};
            float rb[4] = {b0.x, b0.y, b0.z, b0.w};
            #pragma unroll
            for (int i = 0; i < 8; i++)
                #pragma unroll
                for (int j = 0; j < 4; j++)
                    acc[i][j] += ra[i] * rb[j];
        }
        __syncthreads();
    }

    float4 bv4 = *(const float4*)(bo + n0 + tx * 4);
    #pragma unroll
    for (int i = 0; i < 8; i++) {
        int m = m0 + ty * 8 + i;
        float4 o;
        o.x = acc[i][0] + bv4.x;
        o.y = acc[i][1] + bv4.y;
        o.z = acc[i][2] + bv4.z;
        o.w = acc[i][3] + bv4.w;
        *(float4*)(out + (size_t)m * DOUT + n0 + tx * 4) = o;
    }
}

// ---------------------------------------------------------------------------
extern "C" void kernel_launch(void* const* d_in, const int* in_sizes, int n_in,
                              void* d_out, int out_size)
{
    const float* x  = (const float*)d_in[0];
    const float* Wq = (const float*)d_in[1];
    const float* bq = (const float*)d_in[2];
    const float* Wk = (const float*)d_in[3];
    const float* bk = (const float*)d_in[4];
    const float* Wv = (const float*)d_in[5];
    const float* bv = (const float*)d_in[6];
    const float* Wo = (const float*)d_in[7];
    const float* bo = (const float*)d_in[8];
    float* out = (float*)d_out;

    cudaFuncSetAttribute(attn_kernel,
                         cudaFuncAttributeMaxDynamicSharedMemorySize, 98304);

    qkv_kernel<<<dim3(16, 64, 3), 256>>>(x, Wq, bq, Wk, bk, Wv, bv);
    attn_kernel<<<dim3(16, 64), 256, 98304>>>();
    out_kernel<<<dim3(64, 16), 256>>>(Wo, bo, out);
}

// round 5
// speedup vs baseline: 2.8427x; 2.8427x over previous
#include <cuda_runtime.h>
#include <math_constants.h>
#include <cstdint>

#define BB   4
#define SS   2048
#define DD   1024
#define HH   16
#define DK   64
#define DOUT 1024

// Scratch (static device globals: allocation-free rule)
__device__ float g_Q[(size_t)BB * HH * SS * DK];
__device__ float g_K[(size_t)BB * HH * SS * DK];
__device__ float g_V[(size_t)BB * HH * SS * DK];
__device__ float g_cat[(size_t)BB * SS * HH * DK];

// smem row stride (words) for 64-wide tiles.
// MUST be a multiple of 4 so uint4 (16B) row-base stores stay aligned.
#define PAD 68

// ---------------------------------------------------------------------------
// tf32 helpers
// ---------------------------------------------------------------------------
__device__ __forceinline__ uint32_t f2tf(float x) {
    uint32_t u;
    asm("cvt.rna.tf32.f32 %0, %1;" : "=r"(u) : "f"(x));
    return u;
}
__device__ __forceinline__ uint4 cvt4(float4 v) {
    uint4 u;
    u.x = f2tf(v.x); u.y = f2tf(v.y); u.z = f2tf(v.z); u.w = f2tf(v.w);
    return u;
}
// D += A(16x8,row) * B(8x8,col), tf32 in, f32 acc
__device__ __forceinline__ void mma8(float* c,
                                     uint32_t a0, uint32_t a1, uint32_t a2, uint32_t a3,
                                     uint32_t b0, uint32_t b1) {
    asm volatile(
        "mma.sync.aligned.m16n8k8.row.col.f32.tf32.tf32.f32 "
        "{%0,%1,%2,%3}, {%4,%5,%6,%7}, {%8,%9}, {%0,%1,%2,%3};"
        : "+f"(c[0]), "+f"(c[1]), "+f"(c[2]), "+f"(c[3])
        : "r"(a0), "r"(a1), "r"(a2), "r"(a3), "r"(b0), "r"(b1));
}

// ---------------------------------------------------------------------------
// Kernel 1: QKV projections (tensor core, tf32).
// Per (proj,b,h): out[2048x64] = x_b[2048x1024] @ W_h[1024x64] + bias.
// Block tile 128x64, K-tile 32, 8 warps as 4(M)x2(N), warp tile 32x32.
// ---------------------------------------------------------------------------
__global__ __launch_bounds__(256) void qkv_tc(
    const float* __restrict__ x,
    const float* __restrict__ Wq, const float* __restrict__ bq,
    const float* __restrict__ Wk, const float* __restrict__ bk,
    const float* __restrict__ Wv, const float* __restrict__ bv)
{
    const int proj = blockIdx.z;
    const int bh   = blockIdx.y;
    const int b    = bh >> 4;
    const int h    = bh & 15;
    const int m0   = blockIdx.x * 128;

    const float* W; const float* bias; float* out;
    if (proj == 0)      { W = Wq; bias = bq; out = g_Q; }
    else if (proj == 1) { W = Wk; bias = bk; out = g_K; }
    else                { W = Wv; bias = bv; out = g_V; }
    W    += (size_t)h * DD * DK;
    bias += h * DK;
    out  += ((size_t)bh * SS + m0) * DK;
    const float* A = x + (size_t)b * SS * DD + (size_t)m0 * DD;

    __shared__ uint32_t As[128][36];   // [m][k], stride 36 (mult of 4)
    __shared__ uint32_t Bs[32][PAD];   // [k][n]

    const int tid  = threadIdx.x;
    const int warp = tid >> 5;
    const int lane = tid & 31;
    const int wm   = warp >> 1;        // 0..3
    const int wn   = warp & 1;         // 0..1
    const int g    = lane >> 2;        // 0..7
    const int t4   = lane & 3;         // 0..3

    float acc[2][4][4];
    #pragma unroll
    for (int i = 0; i < 2; i++)
        #pragma unroll
        for (int j = 0; j < 4; j++)
            #pragma unroll
            for (int r = 0; r < 4; r++) acc[i][j][r] = 0.f;

    for (int k0 = 0; k0 < DD; k0 += 32) {
        // A tile 128x32: 1024 float4, 4/thread
        #pragma unroll
        for (int u = 0; u < 4; u++) {
            int idx = tid + u * 256;
            int row = idx >> 3;
            int c4  = idx & 7;
            float4 v = *(const float4*)(A + (size_t)row * DD + k0 + c4 * 4);
            *(uint4*)&As[row][c4 * 4] = cvt4(v);
        }
        // W tile 32x64: 512 float4, 2/thread
        #pragma unroll
        for (int u = 0; u < 2; u++) {
            int idx = tid + u * 256;
            int r   = idx >> 4;
            int c4  = idx & 15;
            float4 v = *(const float4*)(W + (size_t)(k0 + r) * DK + c4 * 4);
            *(uint4*)&Bs[r][c4 * 4] = cvt4(v);
        }
        __syncthreads();

        #pragma unroll
        for (int ks = 0; ks < 4; ks++) {
            int kk = ks * 8;
            uint32_t a[2][4];
            #pragma unroll
            for (int i = 0; i < 2; i++) {
                int row = wm * 32 + i * 16 + g;
                a[i][0] = As[row][kk + t4];
                a[i][1] = As[row + 8][kk + t4];
                a[i][2] = As[row][kk + 4 + t4];
                a[i][3] = As[row + 8][kk + 4 + t4];
            }
            #pragma unroll
            for (int j = 0; j < 4; j++) {
                int col = wn * 32 + j * 8 + g;
                uint32_t b0 = Bs[kk + t4][col];
                uint32_t b1 = Bs[kk + 4 + t4][col];
                mma8(acc[0][j], a[0][0], a[0][1], a[0][2], a[0][3], b0, b1);
                mma8(acc[1][j], a[1][0], a[1][1], a[1][2], a[1][3], b0, b1);
            }
        }
        __syncthreads();
    }

    #pragma unroll
    for (int i = 0; i < 2; i++) {
        int r0 = wm * 32 + i * 16 + g;
        #pragma unroll
        for (int j = 0; j < 4; j++) {
            int cb = wn * 32 + j * 8 + 2 * t4;
            float bx = bias[cb], by = bias[cb + 1];
            float2 o0 = make_float2(acc[i][j][0] + bx, acc[i][j][1] + by);
            float2 o1 = make_float2(acc[i][j][2] + bx, acc[i][j][3] + by);
            *(float2*)(out + (size_t)r0 * DK + cb) = o0;
            *(float2*)(out + (size_t)(r0 + 8) * DK + cb) = o1;
        }
    }
}

// ---------------------------------------------------------------------------
// Kernel 2: flash attention, tensor core tf32.
// 128-query tile per block, 64-key tiles. 8 warps, each owns 16 query rows.
// ---------------------------------------------------------------------------
#define ATTN_SMEM ((128 + 64 + 64 + 128) * PAD * 4)   // 104448 bytes

__global__ __launch_bounds__(256) void attn_tc()
{
    extern __shared__ uint32_t smu[];
    uint32_t* Qs = smu;                  // [128][PAD]
    uint32_t* Ks = Qs + 128 * PAD;       // [64][PAD]   [t][dk]
    uint32_t* Vs = Ks + 64 * PAD;        // [64][PAD]   [t][dk]
    uint32_t* Ps = Vs + 64 * PAD;        // [128][PAD]  [m][t]

    const int bh = blockIdx.y;
    const int b  = bh >> 4;
    const int h  = bh & 15;
    const int q0 = blockIdx.x * 128;

    const float* Qp = g_Q + ((size_t)bh * SS + q0) * DK;
    const float* Kp = g_K + (size_t)bh * SS * DK;
    const float* Vp = g_V + (size_t)bh * SS * DK;

    const int tid  = threadIdx.x;
    const int warp = tid >> 5;
    const int lane = tid & 31;
    const int g    = lane >> 2;
    const int t4   = lane & 3;
    const int rA   = warp * 16 + g;     // query row A; row B = rA + 8

    // Load Q tile 128x64 (scaled by 1/sqrt(dk) here, so S mma needs no scale)
    const float scale = 0.125f;
    #pragma unroll
    for (int u = 0; u < 8; u++) {
        int idx = tid + u * 256;
        int m   = idx >> 4;
        int c4  = idx & 15;
        float4 v = *(const float4*)(Qp + (size_t)m * DK + c4 * 4);
        v.x *= scale; v.y *= scale; v.z *= scale; v.w *= scale;
        *(uint4*)&Qs[m * PAD + c4 * 4] = cvt4(v);
    }

    float o[8][4];
    #pragma unroll
    for (int j = 0; j < 8; j++)
        #pragma unroll
        for (int r = 0; r < 4; r++) o[j][r] = 0.f;
    float mA = -CUDART_INF_F, mB = -CUDART_INF_F, lA = 0.f, lB = 0.f;

    for (int t0 = 0; t0 < SS; t0 += 64) {
        __syncthreads();
        // Load K,V tiles 64x64 each, 4 float4/thread each
        #pragma unroll
        for (int u = 0; u < 4; u++) {
            int idx = tid + u * 256;
            int n   = idx >> 4;
            int c4  = idx & 15;
            float4 kv = *(const float4*)(Kp + (size_t)(t0 + n) * DK + c4 * 4);
            *(uint4*)&Ks[n * PAD + c4 * 4] = cvt4(kv);
            float4 vv = *(const float4*)(Vp + (size_t)(t0 + n) * DK + c4 * 4);
            *(uint4*)&Vs[n * PAD + c4 * 4] = cvt4(vv);
        }
        __syncthreads();

        // S = Qs @ Ks^T : warp computes 16 x 64 over k=64
        float s[8][4];
        #pragma unroll
        for (int j = 0; j < 8; j++)
            #pragma unroll
            for (int r = 0; r < 4; r++) s[j][r] = 0.f;

        #pragma unroll
        for (int ks = 0; ks < 8; ks++) {
            int kk = ks * 8;
            uint32_t a0 = Qs[rA * PAD + kk + t4];
            uint32_t a1 = Qs[(rA + 8) * PAD + kk + t4];
            uint32_t a2 = Qs[rA * PAD + kk + 4 + t4];
            uint32_t a3 = Qs[(rA + 8) * PAD + kk + 4 + t4];
            #pragma unroll
            for (int j = 0; j < 8; j++) {
                int n = j * 8 + g;
                uint32_t b0 = Ks[n * PAD + kk + t4];
                uint32_t b1 = Ks[n * PAD + kk + 4 + t4];
                mma8(s[j], a0, a1, a2, a3, b0, b1);
            }
        }

        // Online softmax. Thread owns cols {2*t4, 2*t4+1} of rows rA, rA+8 per j.
        float mxA = -CUDART_INF_F, mxB = -CUDART_INF_F;
        #pragma unroll
        for (int j = 0; j < 8; j++) {
            mxA = fmaxf(mxA, fmaxf(s[j][0], s[j][1]));
            mxB = fmaxf(mxB, fmaxf(s[j][2], s[j][3]));
        }
        #pragma unroll
        for (int off = 1; off <= 2; off <<= 1) {
            mxA = fmaxf(mxA, __shfl_xor_sync(0xffffffffu, mxA, off));
            mxB = fmaxf(mxB, __shfl_xor_sync(0xffffffffu, mxB, off));
        }
        float nmA = fmaxf(mA, mxA), nmB = fmaxf(mB, mxB);
        float alA = __expf(mA - nmA), alB = __expf(mB - nmB);
        mA = nmA; mB = nmB;

        float smA = 0.f, smB = 0.f;
        #pragma unroll
        for (int j = 0; j < 8; j++) {
            float p0 = __expf(s[j][0] - nmA);
            float p1 = __expf(s[j][1] - nmA);
            float p2 = __expf(s[j][2] - nmB);
            float p3 = __expf(s[j][3] - nmB);
            smA += p0 + p1; smB += p2 + p3;
            int col = j * 8 + 2 * t4;
            uint2 uA = make_uint2(f2tf(p0), f2tf(p1));
            uint2 uB = make_uint2(f2tf(p2), f2tf(p3));
            *(uint2*)&Ps[rA * PAD + col] = uA;
            *(uint2*)&Ps[(rA + 8) * PAD + col] = uB;
        }
        #pragma unroll
        for (int off = 1; off <= 2; off <<= 1) {
            smA += __shfl_xor_sync(0xffffffffu, smA, off);
            smB += __shfl_xor_sync(0xffffffffu, smB, off);
        }
        lA = lA * alA + smA;
        lB = lB * alB + smB;
        #pragma unroll
        for (int j = 0; j < 8; j++) {
            o[j][0] *= alA; o[j][1] *= alA;
            o[j][2] *= alB; o[j][3] *= alB;
        }
        __syncwarp();

        // O += P @ V : 16 x 64 over k(t)=64
        #pragma unroll
        for (int ks = 0; ks < 8; ks++) {
            int kk = ks * 8;
            uint32_t a0 = Ps[rA * PAD + kk + t4];
            uint32_t a1 = Ps[(rA + 8) * PAD + kk + t4];
            uint32_t a2 = Ps[rA * PAD + kk + 4 + t4];
            uint32_t a3 = Ps[(rA + 8) * PAD + kk + 4 + t4];
            #pragma unroll
            for (int j = 0; j < 8; j++) {
                int n = j * 8 + g;
                uint32_t b0 = Vs[(kk + t4) * PAD + n];
                uint32_t b1 = Vs[(kk + 4 + t4) * PAD + n];
                mma8(o[j], a0, a1, a2, a3, b0, b1);
            }
        }
        __syncwarp();   // Ps reads done before next iteration's writes
    }

    // Epilogue: normalize, write to concat layout [B,S,H*DK]
    float ivA = 1.f / lA, ivB = 1.f / lB;
    #pragma unroll
    for (int j = 0; j < 8; j++) {
        int col = j * 8 + 2 * t4;
        float2 oa = make_float2(o[j][0] * ivA, o[j][1] * ivA);
        float2 ob = make_float2(o[j][2] * ivB, o[j][3] * ivB);
        size_t baseA = ((size_t)(b * SS + q0 + rA)) * (HH * DK) + h * DK + col;
        size_t baseB = ((size_t)(b * SS + q0 + rA + 8)) * (HH * DK) + h * DK + col;
        *(float2*)(g_cat + baseA) = oa;
        *(float2*)(g_cat + baseB) = ob;
    }
}

// ---------------------------------------------------------------------------
// Kernel 3: output projection, tensor core tf32.
// out[8192x1024] = g_cat @ Wo + bo. Block 128x64, K-tile 32.
// ---------------------------------------------------------------------------
__global__ __launch_bounds__(256) void out_tc(
    const float* __restrict__ Wo, const float* __restrict__ bo,
    float* __restrict__ out)
{
    const int m0 = blockIdx.x * 128;
    const int n0 = blockIdx.y * 64;
    const float* A = g_cat + (size_t)m0 * (HH * DK);

    __shared__ uint32_t As[128][36];
    __shared__ uint32_t Bs[32][PAD];

    const int tid  = threadIdx.x;
    const int warp = tid >> 5;
    const int lane = tid & 31;
    const int wm   = warp >> 1;
    const int wn   = warp & 1;
    const int g    = lane >> 2;
    const int t4   = lane & 3;

    float acc[2][4][4];
    #pragma unroll
    for (int i = 0; i < 2; i++)
        #pragma unroll
        for (int j = 0; j < 4; j++)
            #pragma unroll
            for (int r = 0; r < 4; r++) acc[i][j][r] = 0.f;

    for (int k0 = 0; k0 < HH * DK; k0 += 32) {
        #pragma unroll
        for (int u = 0; u < 4; u++) {
            int idx = tid + u * 256;
            int row = idx >> 3;
            int c4  = idx & 7;
            float4 v = *(const float4*)(A + (size_t)row * (HH * DK) + k0 + c4 * 4);
            *(uint4*)&As[row][c4 * 4] = cvt4(v);
        }
        #pragma unroll
        for (int u = 0; u < 2; u++) {
            int idx = tid + u * 256;
            int r   = idx >> 4;
            int c4  = idx & 15;
            float4 v = *(const float4*)(Wo + (size_t)(k0 + r) * DOUT + n0 + c4 * 4);
            *(uint4*)&Bs[r][c4 * 4] = cvt4(v);
        }
        __syncthreads();

        #pragma unroll
        for (int ks = 0; ks < 4; ks++) {
            int kk = ks * 8;
            uint32_t a[2][4];
            #pragma unroll
            for (int i = 0; i < 2; i++) {
                int row = wm * 32 + i * 16 + g;
                a[i][0] = As[row][kk + t4];
                a[i][1] = As[row + 8][kk + t4];
                a[i][2] = As[row][kk + 4 + t4];
                a[i][3] = As[row + 8][kk + 4 + t4];
            }
            #pragma unroll
            for (int j = 0; j < 4; j++) {
                int col = wn * 32 + j * 8 + g;
                uint32_t b0 = Bs[kk + t4][col];
                uint32_t b1 = Bs[kk + 4 + t4][col];
                mma8(acc[0][j], a[0][0], a[0][1], a[0][2], a[0][3], b0, b1);
                mma8(acc[1][j], a[1][0], a[1][1], a[1][2], a[1][3], b0, b1);
            }
        }
        __syncthreads();
    }

    #pragma unroll
    for (int i = 0; i < 2; i++) {
        int r0 = m0 + wm * 32 + i * 16 + g;
        #pragma unroll
        for (int j = 0; j < 4; j++) {
            int cb = n0 + wn * 32 + j * 8 + 2 * t4;
            float bx = bo[cb], by = bo[cb + 1];
            float2 o0 = make_float2(acc[i][j][0] + bx, acc[i][j][1] + by);
            float2 o1 = make_float2(acc[i][j][2] + bx, acc[i][j][3] + by);
            *(float2*)(out + (size_t)r0 * DOUT + cb) = o0;
            *(float2*)(out + (size_t)(r0 + 8) * DOUT + cb) = o1;
        }
    }
}

// ---------------------------------------------------------------------------
extern "C" void kernel_launch(void* const* d_in, const int* in_sizes, int n_in,
                              void* d_out, int out_size)
{
    const float* x  = (const float*)d_in[0];
    const float* Wq = (const float*)d_in[1];
    const float* bq = (const float*)d_in[2];
    const float* Wk = (const float*)d_in[3];
    const float* bk = (const float*)d_in[4];
    const float* Wv = (const float*)d_in[5];
    const float* bv = (const float*)d_in[6];
    const float* Wo = (const float*)d_in[7];
    const float* bo = (const float*)d_in[8];
    float* out = (float*)d_out;

    // Unconditional (no static guards — harness contract): immediate driver
    // call, identical on every invocation, legal during graph capture.
    cudaFuncSetAttribute(attn_tc,
                         cudaFuncAttributeMaxDynamicSharedMemorySize, ATTN_SMEM);

    qkv_tc<<<dim3(16, 64, 3), 256>>>(x, Wq, bq, Wk, bk, Wv, bv);
    attn_tc<<<dim3(16, 64), 256, ATTN_SMEM>>>();
    out_tc<<<dim3(64, 16), 256>>>(Wo, bo, out);
}

// round 6
// speedup vs baseline: 3.2109x; 1.1295x over previous
#include <cuda_runtime.h>
#include <math_constants.h>
#include <cstdint>

#define BB   4
#define SS   2048
#define DD   1024
#define HH   16
#define DK   64
#define DOUT 1024

// Scratch (static device globals: allocation-free rule)
__device__ float g_Q[(size_t)BB * HH * SS * DK];
__device__ float g_K[(size_t)BB * HH * SS * DK];
__device__ float g_V[(size_t)BB * HH * SS * DK];
__device__ float g_cat[(size_t)BB * SS * HH * DK];

// ---------------------------------------------------------------------------
// tf32 helpers
// ---------------------------------------------------------------------------
__device__ __forceinline__ uint32_t f2tf(float x) {
    uint32_t u;
    asm("cvt.rna.tf32.f32 %0, %1;" : "=r"(u) : "f"(x));
    return u;
}
__device__ __forceinline__ uint4 cvt4(float4 v) {
    uint4 u;
    u.x = f2tf(v.x); u.y = f2tf(v.y); u.z = f2tf(v.z); u.w = f2tf(v.w);
    return u;
}
__device__ __forceinline__ void mma8(float* c,
                                     uint32_t a0, uint32_t a1, uint32_t a2, uint32_t a3,
                                     uint32_t b0, uint32_t b1) {
    asm volatile(
        "mma.sync.aligned.m16n8k8.row.col.f32.tf32.tf32.f32 "
        "{%0,%1,%2,%3}, {%4,%5,%6,%7}, {%8,%9}, {%0,%1,%2,%3};"
        : "+f"(c[0]), "+f"(c[1]), "+f"(c[2]), "+f"(c[3])
        : "r"(a0), "r"(a1), "r"(a2), "r"(a3), "r"(b0), "r"(b1));
}

// B-tile XOR swizzle: word (k,n) stored at column n ^ ((k&3)*8).
// With row stride % 32 == 0 the fragment gather (lanes g=0..7, t4=0..3)
// hits banks ((j^t4)&3)*8 + g  -> all 32 distinct -> conflict-free.
#define BSWZ(k, n) ((n) ^ (((k) & 3) << 3))

// ---------------------------------------------------------------------------
// Kernel 1: fused QKV projection.  Per (b,h):
//   [Q|K|V][2048x64] = x_b[2048x1024] @ [Wq|Wk|Wv]_h[1024x64] + bias
// Block tile 128x192, K-tile 32. 8 warps = 4(M) x 2(N); warp tile 32x96.
// A fragments amortized over 12 N-columns (LDS/mma 1.33 vs 2.0).
// ---------------------------------------------------------------------------
__global__ __launch_bounds__(256, 1) void qkv_tc(
    const float* __restrict__ x,
    const float* __restrict__ Wq, const float* __restrict__ bq,
    const float* __restrict__ Wk, const float* __restrict__ bk,
    const float* __restrict__ Wv, const float* __restrict__ bv)
{
    const int bh = blockIdx.y;
    const int b  = bh >> 4;
    const int h  = bh & 15;
    const int m0 = blockIdx.x * 128;

    const float* A = x + (size_t)b * SS * DD + (size_t)m0 * DD;
    const float* Wp[3] = { Wq + (size_t)h * DD * DK,
                           Wk + (size_t)h * DD * DK,
                           Wv + (size_t)h * DD * DK };

    __shared__ uint32_t As[128][36];    // [m][k]
    __shared__ uint32_t Bs[32][192];    // [k][n(Q|K|V)], XOR swizzled

    const int tid  = threadIdx.x;
    const int warp = tid >> 5;
    const int lane = tid & 31;
    const int wm   = warp >> 1;
    const int wn   = warp & 1;
    const int g    = lane >> 2;
    const int t4   = lane & 3;

    float acc[2][12][4];
    #pragma unroll
    for (int i = 0; i < 2; i++)
        #pragma unroll
        for (int j = 0; j < 12; j++)
            #pragma unroll
            for (int r = 0; r < 4; r++) acc[i][j][r] = 0.f;

    for (int k0 = 0; k0 < DD; k0 += 32) {
        // A tile 128x32
        #pragma unroll
        for (int u = 0; u < 4; u++) {
            int idx = tid + u * 256;
            int row = idx >> 3;
            int c4  = idx & 7;
            float4 v = *(const float4*)(A + (size_t)row * DD + k0 + c4 * 4);
            *(uint4*)&As[row][c4 * 4] = cvt4(v);
        }
        // B tile 32x192 (Wq|Wk|Wv), swizzled
        #pragma unroll
        for (int w = 0; w < 3; w++) {
            #pragma unroll
            for (int u = 0; u < 2; u++) {
                int idx = tid + u * 256;
                int r   = idx >> 4;
                int c4  = idx & 15;
                float4 v = *(const float4*)(Wp[w] + (size_t)(k0 + r) * DK + c4 * 4);
                *(uint4*)&Bs[r][BSWZ(r, w * 64 + c4 * 4)] = cvt4(v);
            }
        }
        __syncthreads();

        #pragma unroll
        for (int ks = 0; ks < 4; ks++) {
            int kk = ks * 8;
            uint32_t bb[12][2];
            #pragma unroll
            for (int j = 0; j < 12; j++) {
                int col = wn * 96 + j * 8 + g;
                int pc  = col ^ (t4 << 3);
                bb[j][0] = Bs[kk + t4][pc];
                bb[j][1] = Bs[kk + 4 + t4][pc];
            }
            #pragma unroll
            for (int i = 0; i < 2; i++) {
                int row = wm * 32 + i * 16 + g;
                uint32_t a0 = As[row][kk + t4];
                uint32_t a1 = As[row + 8][kk + t4];
                uint32_t a2 = As[row][kk + 4 + t4];
                uint32_t a3 = As[row + 8][kk + 4 + t4];
                #pragma unroll
                for (int j = 0; j < 12; j++)
                    mma8(acc[i][j], a0, a1, a2, a3, bb[j][0], bb[j][1]);
            }
        }
        __syncthreads();
    }

    // Epilogue: split columns back to Q/K/V + bias
    #pragma unroll
    for (int j = 0; j < 12; j++) {
        int c    = wn * 96 + j * 8 + 2 * t4;
        int proj = c >> 6;
        int cl   = c & 63;
        float* out = (proj == 0) ? g_Q : (proj == 1) ? g_K : g_V;
        const float* bias = (proj == 0) ? bq : (proj == 1) ? bk : bv;
        out += ((size_t)bh * SS + m0) * DK;
        float bx = bias[h * DK + cl], by = bias[h * DK + cl + 1];
        #pragma unroll
        for (int i = 0; i < 2; i++) {
            int r0 = wm * 32 + i * 16 + g;
            float2 o0 = make_float2(acc[i][j][0] + bx, acc[i][j][1] + by);
            float2 o1 = make_float2(acc[i][j][2] + bx, acc[i][j][3] + by);
            *(float2*)(out + (size_t)r0 * DK + cl) = o0;
            *(float2*)(out + (size_t)(r0 + 8) * DK + cl) = o1;
        }
    }
}

// ---------------------------------------------------------------------------
// Kernel 2: flash attention, tf32 tensor core.
// 256-query tile per block, 64-key tiles. 8 warps, each owns 32 query rows
// (2 m16 tiles) -> K/V fragments amortized over 2 tiles (LDS/mma 1.5).
// ---------------------------------------------------------------------------
#define QT   256
#define QPAD 68
#define ATTN_SMEM ((QT * QPAD + 64 * QPAD + 64 * 64 + QT * QPAD) * 4)

__global__ __launch_bounds__(256, 1) void attn_tc()
{
    extern __shared__ uint32_t smu[];
    uint32_t* Qs = smu;                    // [QT][QPAD]
    uint32_t* Ks = Qs + QT * QPAD;         // [64][QPAD]  [t][dk]
    uint32_t* Vs = Ks + 64 * QPAD;         // [64][64]    [t][dk] XOR swizzled
    uint32_t* Ps = Vs + 64 * 64;           // [QT][QPAD]  [m][t]

    const int bh = blockIdx.y;
    const int b  = bh >> 4;
    const int h  = bh & 15;
    const int q0 = blockIdx.x * QT;

    const float* Qp = g_Q + ((size_t)bh * SS + q0) * DK;
    const float* Kp = g_K + (size_t)bh * SS * DK;
    const float* Vp = g_V + (size_t)bh * SS * DK;

    const int tid  = threadIdx.x;
    const int warp = tid >> 5;
    const int lane = tid & 31;
    const int g    = lane >> 2;
    const int t4   = lane & 3;
    const int r0   = warp * 32 + g;   // rows r0 + {0,8,16,24}

    // Load Q tile QTx64 (pre-scaled by 1/sqrt(dk))
    const float scale = 0.125f;
    #pragma unroll
    for (int u = 0; u < QT / 16; u++) {
        int idx = tid + u * 256;
        int m   = idx >> 4;
        int c4  = idx & 15;
        float4 v = *(const float4*)(Qp + (size_t)m * DK + c4 * 4);
        v.x *= scale; v.y *= scale; v.z *= scale; v.w *= scale;
        *(uint4*)&Qs[m * QPAD + c4 * 4] = cvt4(v);
    }

    float o[2][8][4];
    #pragma unroll
    for (int t = 0; t < 2; t++)
        #pragma unroll
        for (int j = 0; j < 8; j++)
            #pragma unroll
            for (int r = 0; r < 4; r++) o[t][j][r] = 0.f;
    float mrow[4] = {-CUDART_INF_F, -CUDART_INF_F, -CUDART_INF_F, -CUDART_INF_F};
    float lrow[4] = {0.f, 0.f, 0.f, 0.f};

    for (int t0 = 0; t0 < SS; t0 += 64) {
        __syncthreads();
        // K tile (stride QPAD), V tile (stride 64, XOR swizzled)
        #pragma unroll
        for (int u = 0; u < 4; u++) {
            int idx = tid + u * 256;
            int n   = idx >> 4;
            int c4  = idx & 15;
            float4 kv = *(const float4*)(Kp + (size_t)(t0 + n) * DK + c4 * 4);
            *(uint4*)&Ks[n * QPAD + c4 * 4] = cvt4(kv);
            float4 vv = *(const float4*)(Vp + (size_t)(t0 + n) * DK + c4 * 4);
            *(uint4*)&Vs[n * 64 + BSWZ(n, c4 * 4)] = cvt4(vv);
        }
        __syncthreads();

        // S = Q @ K^T : warp computes 32 x 64 over k=64
        float s[2][8][4];
        #pragma unroll
        for (int t = 0; t < 2; t++)
            #pragma unroll
            for (int j = 0; j < 8; j++)
                #pragma unroll
                for (int r = 0; r < 4; r++) s[t][j][r] = 0.f;

        #pragma unroll
        for (int ks = 0; ks < 8; ks++) {
            int kk = ks * 8;
            uint32_t bb[8][2];
            #pragma unroll
            for (int j = 0; j < 8; j++) {
                int n = j * 8 + g;
                bb[j][0] = Ks[n * QPAD + kk + t4];
                bb[j][1] = Ks[n * QPAD + kk + 4 + t4];
            }
            #pragma unroll
            for (int t = 0; t < 2; t++) {
                int rr = r0 + t * 16;
                uint32_t a0 = Qs[rr * QPAD + kk + t4];
                uint32_t a1 = Qs[(rr + 8) * QPAD + kk + t4];
                uint32_t a2 = Qs[rr * QPAD + kk + 4 + t4];
                uint32_t a3 = Qs[(rr + 8) * QPAD + kk + 4 + t4];
                #pragma unroll
                for (int j = 0; j < 8; j++)
                    mma8(s[t][j], a0, a1, a2, a3, bb[j][0], bb[j][1]);
            }
        }

        // Online softmax (4 row groups: 2 per tile)
        #pragma unroll
        for (int t = 0; t < 2; t++) {
            float mx0 = -CUDART_INF_F, mx1 = -CUDART_INF_F;
            #pragma unroll
            for (int j = 0; j < 8; j++) {
                mx0 = fmaxf(mx0, fmaxf(s[t][j][0], s[t][j][1]));
                mx1 = fmaxf(mx1, fmaxf(s[t][j][2], s[t][j][3]));
            }
            #pragma unroll
            for (int off = 1; off <= 2; off <<= 1) {
                mx0 = fmaxf(mx0, __shfl_xor_sync(0xffffffffu, mx0, off));
                mx1 = fmaxf(mx1, __shfl_xor_sync(0xffffffffu, mx1, off));
            }
            int g0 = 2 * t, g1 = 2 * t + 1;
            float nm0 = fmaxf(mrow[g0], mx0), nm1 = fmaxf(mrow[g1], mx1);
            float al0 = __expf(mrow[g0] - nm0), al1 = __expf(mrow[g1] - nm1);
            mrow[g0] = nm0; mrow[g1] = nm1;

            int rr = r0 + t * 16;
            float sm0 = 0.f, sm1 = 0.f;
            #pragma unroll
            for (int j = 0; j < 8; j++) {
                float p0 = __expf(s[t][j][0] - nm0);
                float p1 = __expf(s[t][j][1] - nm0);
                float p2 = __expf(s[t][j][2] - nm1);
                float p3 = __expf(s[t][j][3] - nm1);
                sm0 += p0 + p1; sm1 += p2 + p3;
                int col = j * 8 + 2 * t4;
                *(uint2*)&Ps[rr * QPAD + col] = make_uint2(f2tf(p0), f2tf(p1));
                *(uint2*)&Ps[(rr + 8) * QPAD + col] = make_uint2(f2tf(p2), f2tf(p3));
            }
            #pragma unroll
            for (int off = 1; off <= 2; off <<= 1) {
                sm0 += __shfl_xor_sync(0xffffffffu, sm0, off);
                sm1 += __shfl_xor_sync(0xffffffffu, sm1, off);
            }
            lrow[g0] = lrow[g0] * al0 + sm0;
            lrow[g1] = lrow[g1] * al1 + sm1;
            #pragma unroll
            for (int j = 0; j < 8; j++) {
                o[t][j][0] *= al0; o[t][j][1] *= al0;
                o[t][j][2] *= al1; o[t][j][3] *= al1;
            }
        }
        __syncwarp();

        // O += P @ V : 32 x 64 over k(t)=64
        #pragma unroll
        for (int ks = 0; ks < 8; ks++) {
            int kk = ks * 8;
            uint32_t bb[8][2];
            #pragma unroll
            for (int j = 0; j < 8; j++) {
                int n  = j * 8 + g;
                int pc = n ^ (t4 << 3);
                bb[j][0] = Vs[(kk + t4) * 64 + pc];
                bb[j][1] = Vs[(kk + 4 + t4) * 64 + pc];
            }
            #pragma unroll
            for (int t = 0; t < 2; t++) {
                int rr = r0 + t * 16;
                uint32_t a0 = Ps[rr * QPAD + kk + t4];
                uint32_t a1 = Ps[(rr + 8) * QPAD + kk + t4];
                uint32_t a2 = Ps[rr * QPAD + kk + 4 + t4];
                uint32_t a3 = Ps[(rr + 8) * QPAD + kk + 4 + t4];
                #pragma unroll
                for (int j = 0; j < 8; j++)
                    mma8(o[t][j], a0, a1, a2, a3, bb[j][0], bb[j][1]);
            }
        }
        __syncwarp();
    }

    // Epilogue: normalize, write to concat layout [B,S,H*DK]
    #pragma unroll
    for (int t = 0; t < 2; t++) {
        float iv0 = 1.f / lrow[2 * t], iv1 = 1.f / lrow[2 * t + 1];
        int rr = r0 + t * 16;
        #pragma unroll
        for (int j = 0; j < 8; j++) {
            int col = j * 8 + 2 * t4;
            float2 oa = make_float2(o[t][j][0] * iv0, o[t][j][1] * iv0);
            float2 ob = make_float2(o[t][j][2] * iv1, o[t][j][3] * iv1);
            size_t baseA = ((size_t)(b * SS + q0 + rr)) * (HH * DK) + h * DK + col;
            size_t baseB = ((size_t)(b * SS + q0 + rr + 8)) * (HH * DK) + h * DK + col;
            *(float2*)(g_cat + baseA) = oa;
            *(float2*)(g_cat + baseB) = ob;
        }
    }
}

// ---------------------------------------------------------------------------
// Kernel 3: output projection. out[8192x1024] = g_cat @ Wo + bo.
// Block 128x128, K-tile 32. 8 warps = 4(M) x 2(N); warp tile 32x64.
// ---------------------------------------------------------------------------
__global__ __launch_bounds__(256, 2) void out_tc(
    const float* __restrict__ Wo, const float* __restrict__ bo,
    float* __restrict__ out)
{
    const int m0 = blockIdx.x * 128;
    const int n0 = blockIdx.y * 128;
    const float* A = g_cat + (size_t)m0 * (HH * DK);

    __shared__ uint32_t As[128][36];
    __shared__ uint32_t Bs[32][128];   // XOR swizzled

    const int tid  = threadIdx.x;
    const int warp = tid >> 5;
    const int lane = tid & 31;
    const int wm   = warp >> 1;
    const int wn   = warp & 1;
    const int g    = lane >> 2;
    const int t4   = lane & 3;

    float acc[2][8][4];
    #pragma unroll
    for (int i = 0; i < 2; i++)
        #pragma unroll
        for (int j = 0; j < 8; j++)
            #pragma unroll
            for (int r = 0; r < 4; r++) acc[i][j][r] = 0.f;

    for (int k0 = 0; k0 < HH * DK; k0 += 32) {
        #pragma unroll
        for (int u = 0; u < 4; u++) {
            int idx = tid + u * 256;
            int row = idx >> 3;
            int c4  = idx & 7;
            float4 v = *(const float4*)(A + (size_t)row * (HH * DK) + k0 + c4 * 4);
            *(uint4*)&As[row][c4 * 4] = cvt4(v);
        }
        #pragma unroll
        for (int u = 0; u < 4; u++) {
            int idx = tid + u * 256;
            int r   = idx >> 5;
            int c4  = idx & 31;
            float4 v = *(const float4*)(Wo + (size_t)(k0 + r) * DOUT + n0 + c4 * 4);
            *(uint4*)&Bs[r][BSWZ(r, c4 * 4)] = cvt4(v);
        }
        __syncthreads();

        #pragma unroll
        for (int ks = 0; ks < 4; ks++) {
            int kk = ks * 8;
            uint32_t bb[8][2];
            #pragma unroll
            for (int j = 0; j < 8; j++) {
                int col = wn * 64 + j * 8 + g;
                int pc  = col ^ (t4 << 3);
                bb[j][0] = Bs[kk + t4][pc];
                bb[j][1] = Bs[kk + 4 + t4][pc];
            }
            #pragma unroll
            for (int i = 0; i < 2; i++) {
                int row = wm * 32 + i * 16 + g;
                uint32_t a0 = As[row][kk + t4];
                uint32_t a1 = As[row + 8][kk + t4];
                uint32_t a2 = As[row][kk + 4 + t4];
                uint32_t a3 = As[row + 8][kk + 4 + t4];
                #pragma unroll
                for (int j = 0; j < 8; j++)
                    mma8(acc[i][j], a0, a1, a2, a3, bb[j][0], bb[j][1]);
            }
        }
        __syncthreads();
    }

    #pragma unroll
    for (int i = 0; i < 2; i++) {
        int r0 = m0 + wm * 32 + i * 16 + g;
        #pragma unroll
        for (int j = 0; j < 8; j++) {
            int cb = n0 + wn * 64 + j * 8 + 2 * t4;
            float bx = bo[cb], by = bo[cb + 1];
            float2 o0 = make_float2(acc[i][j][0] + bx, acc[i][j][1] + by);
            float2 o1 = make_float2(acc[i][j][2] + bx, acc[i][j][3] + by);
            *(float2*)(out + (size_t)r0 * DOUT + cb) = o0;
            *(float2*)(out + (size_t)(r0 + 8) * DOUT + cb) = o1;
        }
    }
}

// ---------------------------------------------------------------------------
extern "C" void kernel_launch(void* const* d_in, const int* in_sizes, int n_in,
                              void* d_out, int out_size)
{
    const float* x  = (const float*)d_in[0];
    const float* Wq = (const float*)d_in[1];
    const float* bq = (const float*)d_in[2];
    const float* Wk = (const float*)d_in[3];
    const float* bk = (const float*)d_in[4];
    const float* Wv = (const float*)d_in[5];
    const float* bv = (const float*)d_in[6];
    const float* Wo = (const float*)d_in[7];
    const float* bo = (const float*)d_in[8];
    float* out = (float*)d_out;

    cudaFuncSetAttribute(attn_tc,
                         cudaFuncAttributeMaxDynamicSharedMemorySize, ATTN_SMEM);

    qkv_tc<<<dim3(16, 64), 256>>>(x, Wq, bq, Wk, bk, Wv, bv);
    attn_tc<<<dim3(SS / QT, 64), 256, ATTN_SMEM>>>();
    out_tc<<<dim3(64, 8), 256>>>(Wo, bo, out);
}

// round 8
// speedup vs baseline: 3.7233x; 1.1596x over previous
#include <cuda_runtime.h>
#include <math_constants.h>
#include <cstdint>

#define BB   4
#define SS   2048
#define DD   1024
#define HH   16
#define DK   64
#define DOUT 1024

// Scratch (static device globals: allocation-free rule)
__device__ float g_Q[(size_t)BB * HH * SS * DK];
__device__ float g_K[(size_t)BB * HH * SS * DK];
__device__ float g_V[(size_t)BB * HH * SS * DK];
__device__ float g_cat[(size_t)BB * SS * HH * DK];

// ---------------------------------------------------------------------------
// helpers
// ---------------------------------------------------------------------------
__device__ __forceinline__ uint32_t f2tf(float x) {     // RNA round to tf32
    uint32_t u;
    asm("cvt.rna.tf32.f32 %0, %1;" : "=r"(u) : "f"(x));
    return u;
}
__device__ __forceinline__ float tfr(float x) {         // rounded, as float
    return __uint_as_float(f2tf(x));
}
__device__ __forceinline__ uint32_t cvtw(uint32_t w) {  // raw bits -> tf32 RNA
    return f2tf(__uint_as_float(w));
}
__device__ __forceinline__ void mma8(float* c,
                                     uint32_t a0, uint32_t a1, uint32_t a2, uint32_t a3,
                                     uint32_t b0, uint32_t b1) {
    asm volatile(
        "mma.sync.aligned.m16n8k8.row.col.f32.tf32.tf32.f32 "
        "{%0,%1,%2,%3}, {%4,%5,%6,%7}, {%8,%9}, {%0,%1,%2,%3};"
        : "+f"(c[0]), "+f"(c[1]), "+f"(c[2]), "+f"(c[3])
        : "r"(a0), "r"(a1), "r"(a2), "r"(a3), "r"(b0), "r"(b1));
}

#define CP_ASYNC16(s, g) \
    asm volatile("cp.async.cg.shared.global [%0], [%1], 16;" :: "r"(s), "l"(g))
#define CP_COMMIT() asm volatile("cp.async.commit_group;")
#define CP_WAIT(n)  asm volatile("cp.async.wait_group %0;" :: "n"(n))

__device__ __forceinline__ uint32_t smaddr(const void* p) {
    return (uint32_t)__cvta_generic_to_shared(p);
}

// B-tile XOR swizzle: word (k,n) stored at column n ^ ((k&3)*8).
// Row stride % 32 == 0 -> fragment gathers conflict-free; 16B cp.async chunks
// stay 16B-aligned (mask touches bits 3..4 only).
#define BSWZ(k, n) ((n) ^ (((k) & 3) << 3))

// ---------------------------------------------------------------------------
// Kernel 1: fused QKV projection, cp.async 2-stage pipeline.
// Per (b,h): [Q|K|V][2048x64] = x_b[2048x1024] @ [Wq|Wk|Wv]_h + bias
// Block tile 128x192, K-tile 32. 8 warps = 4(M) x 2(N), warp tile 32x96.
// Fragments RNA-converted in registers (external fp32 inputs).
// Epilogue stores tf32-pre-rounded values so downstream truncation is exact.
// ---------------------------------------------------------------------------
#define QKV_SMEM ((2 * 128 * 36 + 2 * 32 * 192) * 4)   // 86016 B

__global__ __launch_bounds__(256, 1) void qkv_tc(
    const float* __restrict__ x,
    const float* __restrict__ Wq, const float* __restrict__ bq,
    const float* __restrict__ Wk, const float* __restrict__ bk,
    const float* __restrict__ Wv, const float* __restrict__ bv)
{
    extern __shared__ uint32_t dyn[];
    uint32_t* As = dyn;                 // [2][128][36]
    uint32_t* Bs = dyn + 2 * 128 * 36;  // [2][32][192] swizzled

    const int bh = blockIdx.y;
    const int b  = bh >> 4;
    const int h  = bh & 15;
    const int m0 = blockIdx.x * 128;

    const float* A = x + (size_t)b * SS * DD + (size_t)m0 * DD;
    const float* Wp[3] = { Wq + (size_t)h * DD * DK,
                           Wk + (size_t)h * DD * DK,
                           Wv + (size_t)h * DD * DK };

    const int tid  = threadIdx.x;
    const int warp = tid >> 5;
    const int lane = tid & 31;
    const int wm   = warp >> 1;
    const int wn   = warp & 1;
    const int g    = lane >> 2;
    const int t4   = lane & 3;

    float acc[2][12][4];
    #pragma unroll
    for (int i = 0; i < 2; i++)
        #pragma unroll
        for (int j = 0; j < 12; j++)
            #pragma unroll
            for (int r = 0; r < 4; r++) acc[i][j][r] = 0.f;

    auto load_stage = [&](int buf, int k0) {
        uint32_t* Ad = As + buf * 128 * 36;
        uint32_t* Bd = Bs + buf * 32 * 192;
        #pragma unroll
        for (int u = 0; u < 4; u++) {
            int idx = tid + u * 256;
            int row = idx >> 3;
            int c4  = idx & 7;
            CP_ASYNC16(smaddr(&Ad[row * 36 + c4 * 4]),
                       A + (size_t)row * DD + k0 + c4 * 4);
        }
        #pragma unroll
        for (int w = 0; w < 3; w++) {
            #pragma unroll
            for (int u = 0; u < 2; u++) {
                int idx = tid + u * 256;
                int r   = idx >> 4;
                int c4  = idx & 15;
                CP_ASYNC16(smaddr(&Bd[r * 192 + BSWZ(r, w * 64 + c4 * 4)]),
                           Wp[w] + (size_t)(k0 + r) * DK + c4 * 4);
            }
        }
    };

    const int NK = DD / 32;
    load_stage(0, 0);
    CP_COMMIT();

    for (int it = 0; it < NK; it++) {
        int buf = it & 1;
        if (it + 1 < NK) { load_stage(buf ^ 1, (it + 1) * 32); CP_COMMIT(); CP_WAIT(1); }
        else             { CP_WAIT(0); }
        __syncthreads();

        uint32_t* Ab = As + buf * 128 * 36;
        uint32_t* Bb = Bs + buf * 32 * 192;
        #pragma unroll
        for (int ks = 0; ks < 4; ks++) {
            int kk = ks * 8;
            uint32_t bb[12][2];
            #pragma unroll
            for (int j = 0; j < 12; j++) {
                int col = wn * 96 + j * 8 + g;
                int pc  = col ^ (t4 << 3);
                bb[j][0] = cvtw(Bb[(kk + t4) * 192 + pc]);
                bb[j][1] = cvtw(Bb[(kk + 4 + t4) * 192 + pc]);
            }
            #pragma unroll
            for (int i = 0; i < 2; i++) {
                int row = wm * 32 + i * 16 + g;
                uint32_t a0 = cvtw(Ab[row * 36 + kk + t4]);
                uint32_t a1 = cvtw(Ab[(row + 8) * 36 + kk + t4]);
                uint32_t a2 = cvtw(Ab[row * 36 + kk + 4 + t4]);
                uint32_t a3 = cvtw(Ab[(row + 8) * 36 + kk + 4 + t4]);
                #pragma unroll
                for (int j = 0; j < 12; j++)
                    mma8(acc[i][j], a0, a1, a2, a3, bb[j][0], bb[j][1]);
            }
        }
        __syncthreads();
    }

    // Epilogue: split to Q/K/V + bias, stored pre-rounded to tf32
    #pragma unroll
    for (int j = 0; j < 12; j++) {
        int c    = wn * 96 + j * 8 + 2 * t4;
        int proj = c >> 6;
        int cl   = c & 63;
        float* out = (proj == 0) ? g_Q : (proj == 1) ? g_K : g_V;
        const float* bias = (proj == 0) ? bq : (proj == 1) ? bk : bv;
        out += ((size_t)bh * SS + m0) * DK;
        float bx = bias[h * DK + cl], by = bias[h * DK + cl + 1];
        #pragma unroll
        for (int i = 0; i < 2; i++) {
            int r0 = wm * 32 + i * 16 + g;
            float2 o0 = make_float2(tfr(acc[i][j][0] + bx), tfr(acc[i][j][1] + by));
            float2 o1 = make_float2(tfr(acc[i][j][2] + bx), tfr(acc[i][j][3] + by));
            *(float2*)(out + (size_t)r0 * DK + cl) = o0;
            *(float2*)(out + (size_t)(r0 + 8) * DK + cl) = o1;
        }
    }
}

// ---------------------------------------------------------------------------
// Kernel 2: flash attention, cp.async double-buffered K/V.
// 256-query tile, 64-key tiles. 8 warps x 32 query rows.
// Q/K/V already tf32-exact (pre-rounded by qkv_tc) -> no in-loop cvt.
// ---------------------------------------------------------------------------
#define QT   256
#define QPAD 68
#define ATTN_W (QT * QPAD + 2 * 64 * QPAD + 2 * 64 * 64 + QT * QPAD)
#define ATTN_SMEM (ATTN_W * 4)

__global__ __launch_bounds__(256, 1) void attn_tc()
{
    extern __shared__ uint32_t dyn[];
    uint32_t* Qs = dyn;                        // [QT][QPAD]
    uint32_t* Ks = Qs + QT * QPAD;             // [2][64][QPAD]
    uint32_t* Vs = Ks + 2 * 64 * QPAD;         // [2][64][64] swizzled
    uint32_t* Ps = Vs + 2 * 64 * 64;           // [QT][QPAD]

    const int bh = blockIdx.y;
    const int b  = bh >> 4;
    const int h  = bh & 15;
    const int q0 = blockIdx.x * QT;

    const float* Qp = g_Q + ((size_t)bh * SS + q0) * DK;
    const float* Kp = g_K + (size_t)bh * SS * DK;
    const float* Vp = g_V + (size_t)bh * SS * DK;

    const int tid  = threadIdx.x;
    const int warp = tid >> 5;
    const int lane = tid & 31;
    const int g    = lane >> 2;
    const int t4   = lane & 3;
    const int r0   = warp * 32 + g;

    // Load Q tile raw (values tf32-exact; scale folded into softmax)
    #pragma unroll
    for (int u = 0; u < QT / 16; u++) {
        int idx = tid + u * 256;
        int m   = idx >> 4;
        int c4  = idx & 15;
        float4 v = *(const float4*)(Qp + (size_t)m * DK + c4 * 4);
        *(float4*)&Qs[m * QPAD + c4 * 4] = v;
    }

    auto load_kv = [&](int buf, int t0) {
        uint32_t* Kd = Ks + buf * 64 * QPAD;
        uint32_t* Vd = Vs + buf * 64 * 64;
        #pragma unroll
        for (int u = 0; u < 4; u++) {
            int idx = tid + u * 256;
            int n   = idx >> 4;
            int c4  = idx & 15;
            CP_ASYNC16(smaddr(&Kd[n * QPAD + c4 * 4]),
                       Kp + (size_t)(t0 + n) * DK + c4 * 4);
            CP_ASYNC16(smaddr(&Vd[n * 64 + BSWZ(n, c4 * 4)]),
                       Vp + (size_t)(t0 + n) * DK + c4 * 4);
        }
    };

    float o[2][8][4];
    #pragma unroll
    for (int t = 0; t < 2; t++)
        #pragma unroll
        for (int j = 0; j < 8; j++)
            #pragma unroll
            for (int r = 0; r < 4; r++) o[t][j][r] = 0.f;
    float mrow[4] = {-CUDART_INF_F, -CUDART_INF_F, -CUDART_INF_F, -CUDART_INF_F};
    float lrow[4] = {0.f, 0.f, 0.f, 0.f};

    const float scale = 0.125f;
    const int NT = SS / 64;
    load_kv(0, 0);
    CP_COMMIT();

    for (int it = 0; it < NT; it++) {
        int buf = it & 1;
        if (it + 1 < NT) { load_kv(buf ^ 1, (it + 1) * 64); CP_COMMIT(); CP_WAIT(1); }
        else             { CP_WAIT(0); }
        __syncthreads();

        uint32_t* Kb = Ks + buf * 64 * QPAD;
        uint32_t* Vb = Vs + buf * 64 * 64;

        // S = Q @ K^T : warp computes 32 x 64 over k=64
        float s[2][8][4];
        #pragma unroll
        for (int t = 0; t < 2; t++)
            #pragma unroll
            for (int j = 0; j < 8; j++)
                #pragma unroll
                for (int r = 0; r < 4; r++) s[t][j][r] = 0.f;

        #pragma unroll
        for (int ks = 0; ks < 8; ks++) {
            int kk = ks * 8;
            uint32_t bb[8][2];
            #pragma unroll
            for (int j = 0; j < 8; j++) {
                int n = j * 8 + g;
                bb[j][0] = Kb[n * QPAD + kk + t4];
                bb[j][1] = Kb[n * QPAD + kk + 4 + t4];
            }
            #pragma unroll
            for (int t = 0; t < 2; t++) {
                int rr = r0 + t * 16;
                uint32_t a0 = Qs[rr * QPAD + kk + t4];
                uint32_t a1 = Qs[(rr + 8) * QPAD + kk + t4];
                uint32_t a2 = Qs[rr * QPAD + kk + 4 + t4];
                uint32_t a3 = Qs[(rr + 8) * QPAD + kk + 4 + t4];
                #pragma unroll
                for (int j = 0; j < 8; j++)
                    mma8(s[t][j], a0, a1, a2, a3, bb[j][0], bb[j][1]);
            }
        }

        // Online softmax (scale folded here); P stored RNA-rounded
        #pragma unroll
        for (int t = 0; t < 2; t++) {
            #pragma unroll
            for (int j = 0; j < 8; j++)
                #pragma unroll
                for (int r = 0; r < 4; r++) s[t][j][r] *= scale;

            float mx0 = -CUDART_INF_F, mx1 = -CUDART_INF_F;
            #pragma unroll
            for (int j = 0; j < 8; j++) {
                mx0 = fmaxf(mx0, fmaxf(s[t][j][0], s[t][j][1]));
                mx1 = fmaxf(mx1, fmaxf(s[t][j][2], s[t][j][3]));
            }
            #pragma unroll
            for (int off = 1; off <= 2; off <<= 1) {
                mx0 = fmaxf(mx0, __shfl_xor_sync(0xffffffffu, mx0, off));
                mx1 = fmaxf(mx1, __shfl_xor_sync(0xffffffffu, mx1, off));
            }
            int g0 = 2 * t, g1 = 2 * t + 1;
            float nm0 = fmaxf(mrow[g0], mx0), nm1 = fmaxf(mrow[g1], mx1);
            float al0 = __expf(mrow[g0] - nm0), al1 = __expf(mrow[g1] - nm1);
            mrow[g0] = nm0; mrow[g1] = nm1;

            int rr = r0 + t * 16;
            float sm0 = 0.f, sm1 = 0.f;
            #pragma unroll
            for (int j = 0; j < 8; j++) {
                float p0 = __expf(s[t][j][0] - nm0);
                float p1 = __expf(s[t][j][1] - nm0);
                float p2 = __expf(s[t][j][2] - nm1);
                float p3 = __expf(s[t][j][3] - nm1);
                sm0 += p0 + p1; sm1 += p2 + p3;
                int col = j * 8 + 2 * t4;
                *(uint2*)&Ps[rr * QPAD + col] = make_uint2(f2tf(p0), f2tf(p1));
                *(uint2*)&Ps[(rr + 8) * QPAD + col] = make_uint2(f2tf(p2), f2tf(p3));
            }
            #pragma unroll
            for (int off = 1; off <= 2; off <<= 1) {
                sm0 += __shfl_xor_sync(0xffffffffu, sm0, off);
                sm1 += __shfl_xor_sync(0xffffffffu, sm1, off);
            }
            lrow[g0] = lrow[g0] * al0 + sm0;
            lrow[g1] = lrow[g1] * al1 + sm1;
            #pragma unroll
            for (int j = 0; j < 8; j++) {
                o[t][j][0] *= al0; o[t][j][1] *= al0;
                o[t][j][2] *= al1; o[t][j][3] *= al1;
            }
        }
        __syncwarp();

        // O += P @ V : 32 x 64 over k(t)=64
        #pragma unroll
        for (int ks = 0; ks < 8; ks++) {
            int kk = ks * 8;
            uint32_t bb[8][2];
            #pragma unroll
            for (int j = 0; j < 8; j++) {
                int n  = j * 8 + g;
                int pc = n ^ (t4 << 3);
                bb[j][0] = Vb[(kk + t4) * 64 + pc];
                bb[j][1] = Vb[(kk + 4 + t4) * 64 + pc];
            }
            #pragma unroll
            for (int t = 0; t < 2; t++) {
                int rr = r0 + t * 16;
                uint32_t a0 = Ps[rr * QPAD + kk + t4];
                uint32_t a1 = Ps[(rr + 8) * QPAD + kk + t4];
                uint32_t a2 = Ps[rr * QPAD + kk + 4 + t4];
                uint32_t a3 = Ps[(rr + 8) * QPAD + kk + 4 + t4];
                #pragma unroll
                for (int j = 0; j < 8; j++)
                    mma8(o[t][j], a0, a1, a2, a3, bb[j][0], bb[j][1]);
            }
        }
        __syncthreads();   // compute done before next cp.async overwrites buf
    }

    // Epilogue: normalize, store pre-rounded to tf32 in concat layout
    #pragma unroll
    for (int t = 0; t < 2; t++) {
        float iv0 = 1.f / lrow[2 * t], iv1 = 1.f / lrow[2 * t + 1];
        int rr = r0 + t * 16;
        #pragma unroll
        for (int j = 0; j < 8; j++) {
            int col = j * 8 + 2 * t4;
            float2 oa = make_float2(tfr(o[t][j][0] * iv0), tfr(o[t][j][1] * iv0));
            float2 ob = make_float2(tfr(o[t][j][2] * iv1), tfr(o[t][j][3] * iv1));
            size_t baseA = ((size_t)(b * SS + q0 + rr)) * (HH * DK) + h * DK + col;
            size_t baseB = ((size_t)(b * SS + q0 + rr + 8)) * (HH * DK) + h * DK + col;
            *(float2*)(g_cat + baseA) = oa;
            *(float2*)(g_cat + baseB) = ob;
        }
    }
}

// ---------------------------------------------------------------------------
// Kernel 3: output projection, cp.async 2-stage.
// out[8192x1024] = g_cat @ Wo + bo. Block 128x128, K-tile 32.
// A (g_cat) tf32-exact; Wo fragments RNA-converted in registers.
// ---------------------------------------------------------------------------
#define OUT_SMEM ((2 * 128 * 36 + 2 * 32 * 128) * 4)   // 69632 B

__global__ __launch_bounds__(256, 2) void out_tc(
    const float* __restrict__ Wo, const float* __restrict__ bo,
    float* __restrict__ out)
{
    extern __shared__ uint32_t dyn[];
    uint32_t* As = dyn;                 // [2][128][36]
    uint32_t* Bs = dyn + 2 * 128 * 36;  // [2][32][128] swizzled

    const int m0 = blockIdx.x * 128;
    const int n0 = blockIdx.y * 128;
    const float* A = g_cat + (size_t)m0 * (HH * DK);

    const int tid  = threadIdx.x;
    const int warp = tid >> 5;
    const int lane = tid & 31;
    const int wm   = warp >> 1;
    const int wn   = warp & 1;
    const int g    = lane >> 2;
    const int t4   = lane & 3;

    float acc[2][8][4];
    #pragma unroll
    for (int i = 0; i < 2; i++)
        #pragma unroll
        for (int j = 0; j < 8; j++)
            #pragma unroll
            for (int r = 0; r < 4; r++) acc[i][j][r] = 0.f;

    auto load_stage = [&](int buf, int k0) {
        uint32_t* Ad = As + buf * 128 * 36;
        uint32_t* Bd = Bs + buf * 32 * 128;
        #pragma unroll
        for (int u = 0; u < 4; u++) {
            int idx = tid + u * 256;
            int row = idx >> 3;
            int c4  = idx & 7;
            CP_ASYNC16(smaddr(&Ad[row * 36 + c4 * 4]),
                       A + (size_t)row * (HH * DK) + k0 + c4 * 4);
        }
        #pragma unroll
        for (int u = 0; u < 4; u++) {
            int idx = tid + u * 256;
            int r   = idx >> 5;
            int c4  = idx & 31;
            CP_ASYNC16(smaddr(&Bd[r * 128 + BSWZ(r, c4 * 4)]),
                       Wo + (size_t)(k0 + r) * DOUT + n0 + c4 * 4);
        }
    };

    const int NK = (HH * DK) / 32;
    load_stage(0, 0);
    CP_COMMIT();

    for (int it = 0; it < NK; it++) {
        int buf = it & 1;
        if (it + 1 < NK) { load_stage(buf ^ 1, (it + 1) * 32); CP_COMMIT(); CP_WAIT(1); }
        else             { CP_WAIT(0); }
        __syncthreads();

        uint32_t* Ab = As + buf * 128 * 36;
        uint32_t* Bb = Bs + buf * 32 * 128;
        #pragma unroll
        for (int ks = 0; ks < 4; ks++) {
            int kk = ks * 8;
            uint32_t bb[8][2];
            #pragma unroll
            for (int j = 0; j < 8; j++) {
                int col = wn * 64 + j * 8 + g;
                int pc  = col ^ (t4 << 3);
                bb[j][0] = cvtw(Bb[(kk + t4) * 128 + pc]);
                bb[j][1] = cvtw(Bb[(kk + 4 + t4) * 128 + pc]);
            }
            #pragma unroll
            for (int i = 0; i < 2; i++) {
                int row = wm * 32 + i * 16 + g;
                uint32_t a0 = Ab[row * 36 + kk + t4];
                uint32_t a1 = Ab[(row + 8) * 36 + kk + t4];
                uint32_t a2 = Ab[row * 36 + kk + 4 + t4];
                uint32_t a3 = Ab[(row + 8) * 36 + kk + 4 + t4];
                #pragma unroll
                for (int j = 0; j < 8; j++)
                    mma8(acc[i][j], a0, a1, a2, a3, bb[j][0], bb[j][1]);
            }
        }
        __syncthreads();
    }

    #pragma unroll
    for (int i = 0; i < 2; i++) {
        int r0 = m0 + wm * 32 + i * 16 + g;
        #pragma unroll
        for (int j = 0; j < 8; j++) {
            int cb = n0 + wn * 64 + j * 8 + 2 * t4;
            float bx = bo[cb], by = bo[cb + 1];
            float2 o0 = make_float2(acc[i][j][0] + bx, acc[i][j][1] + by);
            float2 o1 = make_float2(acc[i][j][2] + bx, acc[i][j][3] + by);
            *(float2*)(out + (size_t)r0 * DOUT + cb) = o0;
            *(float2*)(out + (size_t)(r0 + 8) * DOUT + cb) = o1;
        }
    }
}

// ---------------------------------------------------------------------------
extern "C" void kernel_launch(void* const* d_in, const int* in_sizes, int n_in,
                              void* d_out, int out_size)
{
    const float* x  = (const float*)d_in[0];
    const float* Wq = (const float*)d_in[1];
    const float* bq = (const float*)d_in[2];
    const float* Wk = (const float*)d_in[3];
    const float* bk = (const float*)d_in[4];
    const float* Wv = (const float*)d_in[5];
    const float* bv = (const float*)d_in[6];
    const float* Wo = (const float*)d_in[7];
    const float* bo = (const float*)d_in[8];
    float* out = (float*)d_out;

    cudaFuncSetAttribute(qkv_tc,
                         cudaFuncAttributeMaxDynamicSharedMemorySize, QKV_SMEM);
    cudaFuncSetAttribute(attn_tc,
                         cudaFuncAttributeMaxDynamicSharedMemorySize, ATTN_SMEM);
    cudaFuncSetAttribute(out_tc,
                         cudaFuncAttributeMaxDynamicSharedMemorySize, OUT_SMEM);

    qkv_tc<<<dim3(16, 64), 256, QKV_SMEM>>>(x, Wq, bq, Wk, bk, Wv, bv);
    attn_tc<<<dim3(SS / QT, 64), 256, ATTN_SMEM>>>();
    out_tc<<<dim3(64, 8), 256, OUT_SMEM>>>(Wo, bo, out);
}